// round 7
// baseline (speedup 1.0000x reference)
#include <cuda_runtime.h>
#include <cooperative_groups.h>
#include <math.h>
namespace cg = cooperative_groups;

#define TGT 20
#define BATCH 64
#define BLOCK 512
#define NWARP 16
#define CLUSTER 4
#define NCLUST (3 * BATCH)

// dynamic smem layout (bytes) — per CTA (one stripe, max 2352 anchors)
#define OFF_KEY  0          // ull[2352] 18816 (pad 18944)
#define OFF_BCE  18944      // f32[2352]  9408
#define OFF_OV   28352      // u8[2352]   2352 (pad to 30720)
#define OFF_HIST 30720      // u32[2048]  8192
#define SMEM_BYTES 38912

struct Sh {
    float tb[TGT][4];
    float tarea[TGT];
    int   tlab[TGT];
    unsigned long long best[TGT];
    unsigned long long cbest[TGT];
    float wred[NWARP][8];
    float out[8];
    float csum[8];
    unsigned warpTot[NWARP];
    unsigned warpSE[NWARP];
    int selBucket;
    unsigned selAbove;
    int isLast;
};

__device__ float g_partials[NCLUST * 3];
__device__ unsigned g_done = 0;

template<int N>
__device__ __forceinline__ void redN(float* v, Sh& sh) {
    int lane = threadIdx.x & 31, wid = threadIdx.x >> 5;
    #pragma unroll
    for (int i = 0; i < N; i++) {
        float x = v[i];
        #pragma unroll
        for (int off = 16; off; off >>= 1) x += __shfl_xor_sync(0xffffffffu, x, off);
        if (lane == 0) sh.wred[wid][i] = x;
    }
    __syncthreads();
    if (threadIdx.x < N) {
        float s = 0.f;
        #pragma unroll
        for (int w = 0; w < NWARP; w++) s += sh.wred[w][threadIdx.x];
        sh.out[threadIdx.x] = s;
    }
    __syncthreads();
}

// cluster-combined bucket select: every CTA reads all 4 peers' hist and
// computes the identical selection (descending / top-k semantics).
template<int NB>
__device__ void selectC(cg::cluster_group& cluster, unsigned* hist, int kRem, Sh& sh) {
    const int tid = threadIdx.x;
    constexpr int CH = NB / BLOCK;   // 4 (NB=2048) or 1 (NB=512)
    int basei = tid * CH;
    unsigned cv[CH];
    #pragma unroll
    for (int j = 0; j < CH; j++) cv[j] = 0;
    #pragma unroll
    for (int r = 0; r < CLUSTER; r++) {
        const unsigned* ph = (const unsigned*)cluster.map_shared_rank(hist, r);
        #pragma unroll
        for (int j = 0; j < CH; j++) cv[j] += ph[basei + j];
    }
    unsigned ls = 0;
    #pragma unroll
    for (int j = 0; j < CH; j++) ls += cv[j];
    int lane = tid & 31, wid = tid >> 5;
    unsigned v = ls;
    #pragma unroll
    for (int off = 1; off < 32; off <<= 1) {
        unsigned w2 = __shfl_down_sync(0xffffffffu, v, off);
        if (lane + off < 32) v += w2;
    }
    if (lane == 0) sh.warpTot[wid] = v;
    __syncthreads();
    if (tid < NWARP) {
        unsigned wv = sh.warpTot[tid];
        unsigned ws = wv;
        #pragma unroll
        for (int off = 1; off < NWARP; off <<= 1) {
            unsigned w2 = __shfl_down_sync(0x0000ffffu, ws, off);
            if (tid + off < NWARP) ws += w2;
        }
        sh.warpSE[tid] = ws - wv;
    }
    __syncthreads();
    unsigned SE = sh.warpSE[wid] + (v - ls);   // count in strictly higher bins
    if (SE < (unsigned)kRem && SE + ls >= (unsigned)kRem) {
        unsigned c = SE;
        #pragma unroll
        for (int j = CH - 1; j >= 0; j--) {
            if (c + cv[j] >= (unsigned)kRem) { sh.selBucket = basei + j; sh.selAbove = c; break; }
            c += cv[j];
        }
    }
    __syncthreads();
}

template<int F>
__device__ void run_scale(const float* __restrict__ pred,
                          const float* __restrict__ tb,
                          const int* __restrict__ tl,
                          float* __restrict__ out,
                          int b, int scale, int rank,
                          unsigned char* dyn, Sh& sh, cg::cluster_group& cluster)
{
    constexpr int FSQ = F * F;
    constexpr float STRIDE = 448.0f / (float)F;
    const int rowLo = (F * rank) / CLUSTER;
    const int rowHi = (F * (rank + 1)) / CLUSTER;
    const int SA = (rowHi - rowLo) * F * 3;
    const int aBase = rowLo * F * 3;

    unsigned long long* s_key = (unsigned long long*)(dyn + OFF_KEY);
    float* s_bce = (float*)(dyn + OFF_BCE);
    unsigned char* s_ov = dyn + OFF_OV;
    unsigned* hist = (unsigned*)(dyn + OFF_HIST);

    const int tid = threadIdx.x;
    if (tid < TGT) {
        const float* p = tb + (size_t)(b * TGT + tid) * 4;
        float x1 = p[0], y1 = p[1], x2 = p[2], y2 = p[3];
        sh.tb[tid][0] = x1; sh.tb[tid][1] = y1; sh.tb[tid][2] = x2; sh.tb[tid][3] = y2;
        sh.tarea[tid] = (x2 - x1) * (y2 - y1);
        sh.tlab[tid] = tl[b * TGT + tid];
        sh.best[tid] = 0ull;
    }
    for (int i = tid; i < SA; i += BLOCK) { s_key[i] = 0ull; s_ov[i] = 0xff; }
    for (int i = tid; i < 2048; i += BLOCK) hist[i] = 0;
    __syncthreads();

    const float* predb = pred + (size_t)b * 24 * FSQ;

    // ---------- Phase 1: sparse IoU scatter, clamped to own stripe ----------
    const float half3 = 1.5f * STRIDE;
    for (int t = 0; t < TGT; t++) {
        float tx1 = sh.tb[t][0], ty1 = sh.tb[t][1];
        float tx2 = sh.tb[t][2], ty2 = sh.tb[t][3];
        float ta = sh.tarea[t];
        int c0 = max(0, (int)floorf((tx1 - half3) / STRIDE - 0.5f));
        int c1 = min(F - 1, (int)ceilf((tx2 + half3) / STRIDE - 0.5f));
        int r0 = max(rowLo, (int)floorf((ty1 - half3) / STRIDE - 0.5f));
        int r1 = min(rowHi - 1, (int)ceilf((ty2 + half3) / STRIDE - 0.5f));
        if (c1 < c0 || r1 < r0) continue;
        int w = c1 - c0 + 1, hh = r1 - r0 + 1;
        int n = w * hh;
        unsigned long long bt = 0ull;
        for (int i = tid; i < n; i += BLOCK) {
            int rr = i / w, cc = i - rr * w;
            int r = r0 + rr, c = c0 + cc;
            float cx = ((float)c + 0.5f) * STRIDE;
            float cy = ((float)r + 0.5f) * STRIDE;
            int aG = (r * F + c) * 3;
            #pragma unroll
            for (int ai = 0; ai < 3; ai++) {
                float half = (1.0f + 0.25f * (float)ai) * STRIDE;
                float lx = fmaxf(cx - half, tx1), ly = fmaxf(cy - half, ty1);
                float rx = fminf(cx + half, tx2), ry = fminf(cy + half, ty2);
                float iw = rx - lx, ih = ry - ly;
                if (iw > 0.f && ih > 0.f) {
                    float I = iw * ih;
                    float areaA = (2.f * half) * (2.f * half);
                    float U = areaA + ta - I;
                    unsigned ib = __float_as_uint(I / (U + 1e-9f));
                    atomicMax(&s_key[aG + ai - aBase],
                        ((unsigned long long)ib << 32) | (unsigned long long)(255 - t));
                    unsigned long long pk = ((unsigned long long)ib << 32) |
                        (unsigned long long)(0xffffffffu - (unsigned)(aG + ai));
                    if (pk > bt) bt = pk;
                }
            }
        }
        #pragma unroll
        for (int off = 16; off; off >>= 1) {
            unsigned long long o = __shfl_down_sync(0xffffffffu, bt, off);
            if (o > bt) bt = o;
        }
        if ((tid & 31) == 0 && bt) atomicMax(&sh.best[t], bt);
    }
    __syncthreads();
    cluster.sync();

    // combined per-target best across stripes
    if (tid < TGT) {
        unsigned long long m = 0ull;
        #pragma unroll
        for (int r = 0; r < CLUSTER; r++) {
            const Sh* ps = (const Sh*)cluster.map_shared_rank(&sh, r);
            unsigned long long v2 = ps->best[tid];
            if (v2 > m) m = v2;
        }
        sh.cbest[tid] = m;
    }
    __syncthreads();

    // ---------- Phase 2: forced-positive override (last target wins) ----------
    if (tid == 0) {
        #pragma unroll
        for (int t = 0; t < TGT; t++) {
            if (sh.cbest[t]) {
                int a = (int)(0xffffffffu - (unsigned)(sh.cbest[t] & 0xffffffffull));
                int aLoc = a - aBase;
                if (aLoc >= 0 && aLoc < SA) s_ov[aLoc] = (unsigned char)t;
            }
        }
    }
    __syncthreads();

    // ---------- Phase 3: BCE + level-0 hist + positive cls/loc losses ----------
    float acc[5] = {0.f, 0.f, 0.f, 0.f, 0.f}; // posBce, ce, sl, cntPos, cntNeg
    const int nCells = (rowHi - rowLo) * F;
    for (int lc = tid; lc < nCells; lc += BLOCK) {
        int cellG = rowLo * F + lc;
        int row = cellG / F, col = cellG - row * F;
        float cx = ((float)col + 0.5f) * STRIDE;
        float cy = ((float)row + 0.5f) * STRIDE;
        #pragma unroll
        for (int ai = 0; ai < 3; ai++) {
            int aLoc = lc * 3 + ai;
            unsigned long long key = s_key[aLoc];
            float iou = __uint_as_float((unsigned)(key >> 32));
            unsigned char ov = s_ov[aLoc];
            bool forced = (ov != 0xff);
            bool pos = forced || (iou >= 0.5f);
            bool neg = (!forced) && (iou < 0.3f);
            float x = predb[(ai * 8 + 4) * FSQ + cellG];
            float bce = fmaxf(x, 0.f) - (pos ? x : 0.f) + __logf(1.f + __expf(-fabsf(x)));
            s_bce[aLoc] = neg ? -bce : bce;
            if (neg) {
                atomicAdd(&hist[__float_as_uint(bce) >> 20], 1u);
                acc[4] += 1.f;
            }
            if (pos) {
                acc[3] += 1.f; acc[0] += bce;
                int t = forced ? (int)ov : (255 - (int)(key & 0xffull));
                const float* pb = predb + cellG;
                int cs = ai * 8;
                float c0v = pb[(cs + 5) * FSQ], c1v = pb[(cs + 6) * FSQ], c2v = pb[(cs + 7) * FSQ];
                float m = fmaxf(c0v, fmaxf(c1v, c2v));
                float lse = m + logf(expf(c0v - m) + expf(c1v - m) + expf(c2v - m));
                int tg = sh.tlab[t] - 1;
                float ct = (tg == 0) ? c0v : ((tg == 1) ? c1v : c2v);
                acc[1] += lse - ct;
                float half = (1.0f + 0.25f * (float)ai) * STRIDE;
                float aw = 2.f * half;
                float gx1 = sh.tb[t][0], gy1 = sh.tb[t][1];
                float gx2 = sh.tb[t][2], gy2 = sh.tb[t][3];
                float td[4] = { ((gx1 + gx2) * 0.5f - cx) / aw, ((gy1 + gy2) * 0.5f - cy) / aw,
                                logf((gx2 - gx1) / aw), logf((gy2 - gy1) / aw) };
                #pragma unroll
                for (int j = 0; j < 4; j++) {
                    float d = fabsf(pb[(cs + j) * FSQ] - td[j]);
                    acc[2] += (d < 1.f) ? 0.5f * d * d : d - 0.5f;
                }
            }
        }
    }
    redN<5>(acc, sh);
    cluster.sync();                                // S1: sums + hist published

    if (tid < 5) {
        float s = 0.f;
        #pragma unroll
        for (int r = 0; r < CLUSTER; r++) {
            const Sh* ps = (const Sh*)cluster.map_shared_rank(&sh, r);
            s += ps->out[tid];
        }
        sh.csum[tid] = s;
    }
    __syncthreads();
    float rPosBce = sh.csum[0], rCe = sh.csum[1], rSl = sh.csum[2];
    int np = (int)(sh.csum[3] + 0.5f), nn = (int)(sh.csum[4] + 0.5f);
    int k = min(3 * np, nn);                       // identical in all 4 CTAs

    // ---------- Phase 4: hard-negative mining (3-level combined radix) ----------
    float negTop = 0.f;
    if (k > 0) {
        selectC<2048>(cluster, hist, k, sh);       // level 0: bits 30..20
        int Bq = sh.selBucket;
        int kRem = k - (int)sh.selAbove;
        cluster.sync();                            // S2: level-0 hist reads done

        for (int i = tid; i < 2048; i += BLOCK) hist[i] = 0;
        __syncthreads();
        for (int a = tid; a < SA; a += BLOCK) {
            float v = s_bce[a];
            if (v < 0.f) {
                unsigned u = __float_as_uint(-v);
                if ((int)(u >> 20) == Bq) atomicAdd(&hist[(u >> 9) & 0x7ff], 1u);
            }
        }
        __syncthreads();
        cluster.sync();                            // S3
        selectC<2048>(cluster, hist, kRem, sh);    // level 1: bits 19..9
        int B2q = sh.selBucket;
        int kRem2 = kRem - (int)sh.selAbove;
        cluster.sync();                            // S4

        for (int i = tid; i < 512; i += BLOCK) hist[i] = 0;
        __syncthreads();
        for (int a = tid; a < SA; a += BLOCK) {
            float v = s_bce[a];
            if (v < 0.f) {
                unsigned u = __float_as_uint(-v);
                if ((int)(u >> 20) == Bq && (int)((u >> 9) & 0x7ff) == B2q)
                    atomicAdd(&hist[u & 0x1ff], 1u);
            }
        }
        __syncthreads();
        cluster.sync();                            // S5
        selectC<512>(cluster, hist, kRem2, sh);    // level 2: bits 8..0
        unsigned thr_u = ((unsigned)Bq << 20) | ((unsigned)B2q << 9) | (unsigned)sh.selBucket;
        float thr = __uint_as_float(thr_u);

        float sc[2] = {0.f, 0.f};
        for (int a = tid; a < SA; a += BLOCK) {
            float v = s_bce[a];
            if (v < 0.f) {
                unsigned u = __float_as_uint(-v);
                if (u > thr_u) { sc[0] += -v; sc[1] += 1.f; }
            }
        }
        redN<2>(sc, sh);
        cluster.sync();                            // S6: sc published
        if (tid == 0) {
            float s0 = 0.f, s1 = 0.f;
            #pragma unroll
            for (int r = 0; r < CLUSTER; r++) {
                const Sh* ps = (const Sh*)cluster.map_shared_rank(&sh, r);
                s0 += ps->out[0]; s1 += ps->out[1];
            }
            negTop = s0 + (float)(k - (int)s1) * thr;
        }
    }
    cluster.sync();                                // keep peers alive for reads

    // ---------- Phase 5: partials + fused last-cluster finalize (rank 0) ----------
    if (rank != 0) return;
    if (tid == 0) {
        float ol = (rPosBce + negTop) / (float)max(np + k, 1);
        float cl = rCe / (float)max(np, 1);
        float ll = rSl / (float)max(4 * np, 1);
        float* o = &g_partials[(scale * BATCH + b) * 3];
        o[0] = ol; o[1] = cl; o[2] = ll;
        __threadfence();
        unsigned r = atomicAdd(&g_done, 1);
        sh.isLast = (r == NCLUST - 1) ? 1 : 0;
    }
    __syncthreads();
    if (sh.isLast) {
        float v[3] = {0.f, 0.f, 0.f};
        for (int i = tid; i < NCLUST; i += BLOCK) {
            v[0] += g_partials[i * 3 + 0];
            v[1] += g_partials[i * 3 + 1];
            v[2] += g_partials[i * 3 + 2];
        }
        redN<3>(v, sh);
        if (tid == 0) {
            float obj = sh.out[0] / (float)BATCH;
            float cls = sh.out[1] / (float)BATCH;
            float loc = sh.out[2] / (float)BATCH;
            out[0] = obj; out[1] = cls; out[2] = loc;
            out[3] = obj + cls + 2.0f * loc;
            g_done = 0;  // reset for next graph replay
        }
    }
}

__global__ __launch_bounds__(BLOCK) __cluster_dims__(CLUSTER, 1, 1)
void loss_kernel(const float* __restrict__ pred1, const float* __restrict__ pred2,
                 const float* __restrict__ pred3,
                 const float* __restrict__ tb, const int* __restrict__ tl,
                 float* __restrict__ out)
{
    extern __shared__ unsigned char dyn[];
    __shared__ Sh sh;
    cg::cluster_group cluster = cg::this_cluster();
    int rank = (int)cluster.block_rank();
    int b = blockIdx.x / CLUSTER;
    int scale = blockIdx.y;
    if (scale == 0)      run_scale<56>(pred1, tb, tl, out, b, 0, rank, dyn, sh, cluster);
    else if (scale == 1) run_scale<28>(pred2, tb, tl, out, b, 1, rank, dyn, sh, cluster);
    else                 run_scale<14>(pred3, tb, tl, out, b, 2, rank, dyn, sh, cluster);
}

extern "C" void kernel_launch(void* const* d_in, const int* in_sizes, int n_in,
                              void* d_out, int out_size)
{
    const float* pred1 = (const float*)d_in[0];
    const float* pred2 = (const float*)d_in[1];
    const float* pred3 = (const float*)d_in[2];
    const float* tb    = (const float*)d_in[6];
    const int*   tl    = (const int*)d_in[7];

    cudaFuncSetAttribute(loss_kernel, cudaFuncAttributeMaxDynamicSharedMemorySize,
                         SMEM_BYTES);

    dim3 grid(BATCH * CLUSTER, 3);
    loss_kernel<<<grid, BLOCK, SMEM_BYTES>>>(pred1, pred2, pred3, tb, tl, (float*)d_out);
}

// round 8
// speedup vs baseline: 2.8479x; 2.8479x over previous
#include <cuda_runtime.h>
#include <math.h>

#define TGT 20
#define BATCH 64
#define BLOCK 1024
#define NWARP (BLOCK / 32)
#define MAXA 9408
#define NBLK (3 * BATCH)

// dynamic smem layout (bytes)
#define OFF_IOU  0            // u32[MAXA] 37632  exact max-iou bits per anchor
#define OFF_BCE  37632        // f32[MAXA] 37632  (neg sign-encoded)
#define OFF_OV   75264        // u8[MAXA]   9408  (override t or 0xff)
#define OFF_HIST 84672        // u32[2048]  8192
#define SMEM_BYTES 92864

struct Sh {
    float tb[TGT][4];
    float tarea[TGT];
    int   tlab[TGT];
    int   rc0[TGT], rr0[TGT], rw[TGT];
    int   cum[TGT + 1];
    unsigned long long best[TGT];
    float wred[NWARP][8];
    float out[8];
    unsigned warpTot[NWARP];
    unsigned warpSE[NWARP];
    int selBucket;
    unsigned selAbove;
    int isLast;
};

__device__ float g_partials[NBLK * 3];
__device__ unsigned g_done = 0;

template<int N>
__device__ __forceinline__ void redN(float* v, Sh& sh) {
    int lane = threadIdx.x & 31, wid = threadIdx.x >> 5;
    #pragma unroll
    for (int i = 0; i < N; i++) {
        float x = v[i];
        #pragma unroll
        for (int off = 16; off; off >>= 1) x += __shfl_xor_sync(0xffffffffu, x, off);
        if (lane == 0) sh.wred[wid][i] = x;
    }
    __syncthreads();
    if (threadIdx.x < N) {
        float s = 0.f;
        #pragma unroll
        for (int w = 0; w < NWARP; w++) s += sh.wred[w][threadIdx.x];
        sh.out[threadIdx.x] = s;
    }
    __syncthreads();
}

template<int NB>
__device__ void selectBucket(unsigned* hist, int kRem, Sh& sh) {
    const int tid = threadIdx.x;
    constexpr int CH = (NB >= BLOCK) ? NB / BLOCK : 1;
    int basei = tid * CH;
    unsigned ls = 0;
    if (basei < NB)
        #pragma unroll
        for (int j = 0; j < CH; j++) ls += hist[basei + j];
    int lane = tid & 31, wid = tid >> 5;
    unsigned v = ls;
    #pragma unroll
    for (int off = 1; off < 32; off <<= 1) {
        unsigned w2 = __shfl_down_sync(0xffffffffu, v, off);
        if (lane + off < 32) v += w2;
    }
    if (lane == 0) sh.warpTot[wid] = v;
    __syncthreads();
    if (tid < NWARP) {
        unsigned wv = sh.warpTot[tid];
        unsigned ws = wv;
        #pragma unroll
        for (int off = 1; off < NWARP; off <<= 1) {
            unsigned w2 = __shfl_down_sync(0xffffffffu, ws, off);
            if (tid + off < NWARP) ws += w2;
        }
        sh.warpSE[tid] = ws - wv;
    }
    __syncthreads();
    unsigned SE = sh.warpSE[wid] + (v - ls);
    if (basei < NB && SE < (unsigned)kRem && SE + ls >= (unsigned)kRem) {
        unsigned c = SE;
        #pragma unroll
        for (int j = CH - 1; j >= 0; j--) {
            unsigned hv = hist[basei + j];
            if (c + hv >= (unsigned)kRem) { sh.selBucket = basei + j; sh.selAbove = c; break; }
            c += hv;
        }
    }
    __syncthreads();
}

template<int F>
__device__ void run_scale(const float* __restrict__ pred,
                          const float* __restrict__ tb,
                          const int* __restrict__ tl,
                          float* __restrict__ out,
                          int b, int scale,
                          unsigned char* dyn, Sh& sh)
{
    constexpr int FSQ = F * F;
    constexpr int A = FSQ * 3;
    constexpr float STRIDE = 448.0f / (float)F;
    constexpr float INV = (float)F / 448.0f;   // exact (1/8, 1/16, 1/32)

    unsigned* s_iou = (unsigned*)(dyn + OFF_IOU);
    float* s_bce = (float*)(dyn + OFF_BCE);
    unsigned char* s_ov = dyn + OFF_OV;
    unsigned* hist = (unsigned*)(dyn + OFF_HIST);

    const int tid = threadIdx.x;
    const int lane = tid & 31;

    if (tid < TGT) {
        const float* p = tb + (size_t)(b * TGT + tid) * 4;
        float x1 = p[0], y1 = p[1], x2 = p[2], y2 = p[3];
        sh.tb[tid][0] = x1; sh.tb[tid][1] = y1; sh.tb[tid][2] = x2; sh.tb[tid][3] = y2;
        sh.tarea[tid] = (x2 - x1) * (y2 - y1);
        sh.tlab[tid] = tl[b * TGT + tid];
        sh.best[tid] = 0ull;
        const float half3 = 1.5f * STRIDE;
        int c0 = max(0, (int)floorf((x1 - half3) * INV - 0.5f));
        int c1 = min(F - 1, (int)ceilf((x2 + half3) * INV - 0.5f));
        int r0 = max(0, (int)floorf((y1 - half3) * INV - 0.5f));
        int r1 = min(F - 1, (int)ceilf((y2 + half3) * INV - 0.5f));
        int w = c1 - c0 + 1, hh = r1 - r0 + 1;
        sh.rc0[tid] = c0; sh.rr0[tid] = r0;
        sh.rw[tid] = max(w, 1);
        sh.cum[tid] = (w > 0 && hh > 0) ? w * hh : 0;  // temp: size
    }
    for (int a = tid; a < A; a += BLOCK) s_iou[a] = 0u;
    for (int a = tid; a < A; a += BLOCK) s_ov[a] = 0xff;
    for (int i = tid; i < 2048; i += BLOCK) hist[i] = 0;
    __syncthreads();
    if (tid == 0) {
        int s = 0;
        #pragma unroll
        for (int t = 0; t < TGT; t++) { int sz = sh.cum[t]; sh.cum[t] = s; s += sz; }
        sh.cum[TGT] = s;
    }
    __syncthreads();

    const float* predb = pred + (size_t)b * 24 * FSQ;

    // ---------- Phase 1: flattened (target,cell) scatter ----------
    {
        const int total = sh.cum[TGT];
        const int totalP = (total + BLOCK - 1) & ~(BLOCK - 1);
        int tcur = 0;
        for (int idx = tid; idx < totalP; idx += BLOCK) {
            bool valid = idx < total;
            int tt = -1;
            unsigned long long pk = 0ull;
            if (valid) {
                while (idx >= sh.cum[tcur + 1]) tcur++;
                tt = tcur;
                int local = idx - sh.cum[tt];
                int w = sh.rw[tt];
                int rr = local / w, cc = local - rr * w;
                int r = sh.rr0[tt] + rr, c = sh.rc0[tt] + cc;
                float cx = ((float)c + 0.5f) * STRIDE;
                float cy = ((float)r + 0.5f) * STRIDE;
                float tx1 = sh.tb[tt][0], ty1 = sh.tb[tt][1];
                float tx2 = sh.tb[tt][2], ty2 = sh.tb[tt][3];
                float ta = sh.tarea[tt];
                int abase = (r * F + c) * 3;
                #pragma unroll
                for (int ai = 0; ai < 3; ai++) {
                    float half = (1.0f + 0.25f * (float)ai) * STRIDE;
                    float lx = fmaxf(cx - half, tx1), ly = fmaxf(cy - half, ty1);
                    float rx = fminf(cx + half, tx2), ry = fminf(cy + half, ty2);
                    float iw = rx - lx, ih = ry - ly;
                    if (iw > 0.f && ih > 0.f) {
                        float I = iw * ih;
                        float areaA = (2.f * half) * (2.f * half);
                        float U = areaA + ta - I;
                        unsigned ib = __float_as_uint(I / (U + 1e-9f));
                        atomicMax(&s_iou[abase + ai], ib);
                        unsigned long long cand = ((unsigned long long)ib << 32) |
                            (unsigned long long)(0xffffffffu - (unsigned)(abase + ai));
                        if (cand > pk) pk = cand;
                    }
                }
            }
            // segmented (contiguous by tt) inclusive max-scan; highest lane of
            // each segment holds the group max and issues one atomic.
            #pragma unroll
            for (int off = 1; off < 32; off <<= 1) {
                unsigned long long opk = __shfl_up_sync(0xffffffffu, pk, off);
                int ot = __shfl_up_sync(0xffffffffu, tt, off);
                if (lane >= off && ot == tt && opk > pk) pk = opk;
            }
            unsigned mask = __match_any_sync(0xffffffffu, tt);
            int hi = 31 - __clz(mask);
            if (tt >= 0 && lane == hi && pk)
                atomicMax(&sh.best[tt], pk);
        }
    }
    __syncthreads();

    // ---------- Phase 2: forced-positive override (last target wins) ----------
    if (tid == 0) {
        #pragma unroll
        for (int t = 0; t < TGT; t++) {
            if (sh.best[t]) {
                unsigned a = 0xffffffffu - (unsigned)(sh.best[t] & 0xffffffffull);
                s_ov[a] = (unsigned char)t;
            }
        }
    }
    __syncthreads();

    // ---------- Phase 3: BCE + fused level-0 hist + positive losses ----------
    float acc[5] = {0.f, 0.f, 0.f, 0.f, 0.f}; // posBce, ce, sl, cntPos, cntNeg
    constexpr int FSQP = ((FSQ + BLOCK - 1) / BLOCK) * BLOCK;
    for (int cell = tid; cell < FSQP; cell += BLOCK) {
        bool act = cell < FSQ;
        int row = 0, col = 0;
        float cx = 0.f, cy = 0.f;
        if (act) {
            row = cell / F; col = cell - row * F;
            cx = ((float)col + 0.5f) * STRIDE;
            cy = ((float)row + 0.5f) * STRIDE;
        }
        #pragma unroll
        for (int ai = 0; ai < 3; ai++) {
            int a = cell * 3 + ai;
            unsigned ib = 0; unsigned char ov = 0xff; float x = 0.f;
            if (act) { ib = s_iou[a]; ov = s_ov[a]; x = predb[(ai * 8 + 4) * FSQ + cell]; }
            float iou = __uint_as_float(ib);
            bool forced = act && (ov != 0xff);
            bool pos = forced || (act && iou >= 0.5f);
            bool neg = act && !forced && (iou < 0.3f);
            float bce = fmaxf(x, 0.f) - (pos ? x : 0.f) + __logf(1.f + __expf(-fabsf(x)));
            if (act) s_bce[a] = neg ? -bce : bce;
            int bin = neg ? (int)(__float_as_uint(bce) >> 21) : -1;
            unsigned mask = __match_any_sync(0xffffffffu, bin);
            if (bin >= 0) {
                acc[4] += 1.f;
                if (lane == __ffs(mask) - 1) atomicAdd(&hist[bin], (unsigned)__popc(mask));
            }
            if (pos) {
                acc[3] += 1.f; acc[0] += bce;
                int t = 0;
                if (forced) t = (int)ov;
                else {
                    // recompute matched target: first t with bit-equal iou
                    #pragma unroll
                    for (int q = 0; q < TGT; q++) {
                        float half = (1.0f + 0.25f * (float)ai) * STRIDE;
                        float lx = fmaxf(cx - half, sh.tb[q][0]);
                        float ly = fmaxf(cy - half, sh.tb[q][1]);
                        float rx = fminf(cx + half, sh.tb[q][2]);
                        float ry = fminf(cy + half, sh.tb[q][3]);
                        float iw = rx - lx, ih = ry - ly;
                        if (iw > 0.f && ih > 0.f) {
                            float I = iw * ih;
                            float areaA = (2.f * half) * (2.f * half);
                            float U = areaA + sh.tarea[q] - I;
                            if (__float_as_uint(I / (U + 1e-9f)) == ib) { t = q; break; }
                        }
                    }
                }
                const float* pb = predb + cell;
                int cs = ai * 8;
                float c0v = pb[(cs + 5) * FSQ], c1v = pb[(cs + 6) * FSQ], c2v = pb[(cs + 7) * FSQ];
                float m = fmaxf(c0v, fmaxf(c1v, c2v));
                float lse = m + logf(expf(c0v - m) + expf(c1v - m) + expf(c2v - m));
                int tg = sh.tlab[t] - 1;
                float ct = (tg == 0) ? c0v : ((tg == 1) ? c1v : c2v);
                acc[1] += lse - ct;
                float half = (1.0f + 0.25f * (float)ai) * STRIDE;
                float aw = 2.f * half;
                float gx1 = sh.tb[t][0], gy1 = sh.tb[t][1];
                float gx2 = sh.tb[t][2], gy2 = sh.tb[t][3];
                float td[4] = { ((gx1 + gx2) * 0.5f - cx) / aw, ((gy1 + gy2) * 0.5f - cy) / aw,
                                logf((gx2 - gx1) / aw), logf((gy2 - gy1) / aw) };
                #pragma unroll
                for (int j = 0; j < 4; j++) {
                    float d = fabsf(pb[(cs + j) * FSQ] - td[j]);
                    acc[2] += (d < 1.f) ? 0.5f * d * d : d - 0.5f;
                }
            }
        }
    }
    redN<5>(acc, sh);
    float rPosBce = sh.out[0], rCe = sh.out[1], rSl = sh.out[2];
    int np = (int)sh.out[3], nn = (int)sh.out[4];
    int k = min(3 * np, nn);

    // ---------- Phase 4: hard-negative mining (3-level radix select) ----------
    float negTop = 0.f;
    if (k > 0) {
        selectBucket<2048>(hist, k, sh);             // level 0: bits 30..21
        int Bq = sh.selBucket;
        int kRem = k - (int)sh.selAbove;

        for (int i = tid; i < 2048; i += BLOCK) hist[i] = 0;
        __syncthreads();
        for (int a = tid; a < A; a += BLOCK) {
            float v = s_bce[a];
            if (v < 0.f) {
                unsigned u = __float_as_uint(-v);
                if ((int)(u >> 21) == Bq) atomicAdd(&hist[(u >> 10) & 0x7ff], 1u);
            }
        }
        __syncthreads();
        selectBucket<2048>(hist, kRem, sh);          // level 1: bits 20..10
        int B2q = sh.selBucket;
        int kRem2 = kRem - (int)sh.selAbove;

        for (int i = tid; i < 1024; i += BLOCK) hist[i] = 0;
        __syncthreads();
        for (int a = tid; a < A; a += BLOCK) {
            float v = s_bce[a];
            if (v < 0.f) {
                unsigned u = __float_as_uint(-v);
                if ((int)(u >> 21) == Bq && (int)((u >> 10) & 0x7ff) == B2q)
                    atomicAdd(&hist[u & 0x3ff], 1u);
            }
        }
        __syncthreads();
        selectBucket<1024>(hist, kRem2, sh);         // level 2: bits 9..0
        unsigned thr_u = ((unsigned)Bq << 21) | ((unsigned)B2q << 10) | (unsigned)sh.selBucket;
        float thr = __uint_as_float(thr_u);

        float sc[2] = {0.f, 0.f};
        for (int a = tid; a < A; a += BLOCK) {
            float v = s_bce[a];
            if (v < 0.f) {
                unsigned u = __float_as_uint(-v);
                if (u > thr_u) { sc[0] += -v; sc[1] += 1.f; }
            }
        }
        redN<2>(sc, sh);
        negTop = sh.out[0] + (float)(k - (int)sh.out[1]) * thr;
    }

    // ---------- Phase 5: partials + fused last-block finalize ----------
    if (tid == 0) {
        float ol = (rPosBce + negTop) / (float)max(np + k, 1);
        float cl = rCe / (float)max(np, 1);
        float ll = rSl / (float)max(4 * np, 1);
        float* o = &g_partials[(scale * BATCH + b) * 3];
        o[0] = ol; o[1] = cl; o[2] = ll;
        __threadfence();
        unsigned r = atomicAdd(&g_done, 1);
        sh.isLast = (r == NBLK - 1) ? 1 : 0;
    }
    __syncthreads();
    if (sh.isLast) {
        float v[3] = {0.f, 0.f, 0.f};
        for (int i = tid; i < NBLK; i += BLOCK) {
            v[0] += g_partials[i * 3 + 0];
            v[1] += g_partials[i * 3 + 1];
            v[2] += g_partials[i * 3 + 2];
        }
        redN<3>(v, sh);
        if (tid == 0) {
            float obj = sh.out[0] / (float)BATCH;
            float cls = sh.out[1] / (float)BATCH;
            float loc = sh.out[2] / (float)BATCH;
            out[0] = obj; out[1] = cls; out[2] = loc;
            out[3] = obj + cls + 2.0f * loc;
            g_done = 0;  // reset for next graph replay
        }
    }
}

__global__ __launch_bounds__(BLOCK)
void loss_kernel(const float* __restrict__ pred1, const float* __restrict__ pred2,
                 const float* __restrict__ pred3,
                 const float* __restrict__ tb, const int* __restrict__ tl,
                 float* __restrict__ out)
{
    extern __shared__ unsigned char dyn[];
    __shared__ Sh sh;
    int b = blockIdx.x, scale = blockIdx.y;
    if (scale == 0)      run_scale<56>(pred1, tb, tl, out, b, 0, dyn, sh);
    else if (scale == 1) run_scale<28>(pred2, tb, tl, out, b, 1, dyn, sh);
    else                 run_scale<14>(pred3, tb, tl, out, b, 2, dyn, sh);
}

extern "C" void kernel_launch(void* const* d_in, const int* in_sizes, int n_in,
                              void* d_out, int out_size)
{
    const float* pred1 = (const float*)d_in[0];
    const float* pred2 = (const float*)d_in[1];
    const float* pred3 = (const float*)d_in[2];
    const float* tb    = (const float*)d_in[6];
    const int*   tl    = (const int*)d_in[7];

    cudaFuncSetAttribute(loss_kernel, cudaFuncAttributeMaxDynamicSharedMemorySize,
                         SMEM_BYTES);

    dim3 grid(BATCH, 3);
    loss_kernel<<<grid, BLOCK, SMEM_BYTES>>>(pred1, pred2, pred3, tb, tl, (float*)d_out);
}

// round 10
// speedup vs baseline: 2.9605x; 1.0395x over previous
#include <cuda_runtime.h>
#include <math.h>

#define TGT 20
#define BATCH 64
#define BLOCK 1024
#define NWARP (BLOCK / 32)
#define MAXA 9408
#define NBLK (3 * BATCH)

// dynamic smem layout (bytes)
#define OFF_VAL  0            // u32/f32[MAXA] 37632: iou bits -> bce (neg sign-enc)
#define OFF_HIST 37632        // u32[2048]  8192
#define SMEM_BYTES 45824

#define MARK 0x7F800001u      // forced-override marker base (NaN space)

struct Sh {
    float tb[TGT][4];
    float tarea[TGT];
    int   tlab[TGT];
    int   rc0[TGT], rr0[TGT], rw[TGT];
    int   cum[TGT + 1];
    unsigned long long best[TGT];
    float wred[NWARP][8];
    float out[8];
    unsigned warpTot[NWARP];
    unsigned warpSE[NWARP];
    int selBucket;
    unsigned selAbove;
    int isLast;
};

__device__ float g_partials[NBLK * 3];
__device__ unsigned g_done = 0;

template<int N>
__device__ __forceinline__ void redN(float* v, Sh& sh) {
    int lane = threadIdx.x & 31, wid = threadIdx.x >> 5;
    #pragma unroll
    for (int i = 0; i < N; i++) {
        float x = v[i];
        #pragma unroll
        for (int off = 16; off; off >>= 1) x += __shfl_xor_sync(0xffffffffu, x, off);
        if (lane == 0) sh.wred[wid][i] = x;
    }
    __syncthreads();
    if (threadIdx.x < N) {
        float s = 0.f;
        #pragma unroll
        for (int w = 0; w < NWARP; w++) s += sh.wred[w][threadIdx.x];
        sh.out[threadIdx.x] = s;
    }
    __syncthreads();
}

template<int NB>
__device__ void selectBucket(unsigned* hist, int kRem, Sh& sh) {
    const int tid = threadIdx.x;
    constexpr int CH = (NB >= BLOCK) ? NB / BLOCK : 1;
    int basei = tid * CH;
    unsigned ls = 0;
    if (basei < NB)
        #pragma unroll
        for (int j = 0; j < CH; j++) ls += hist[basei + j];
    int lane = tid & 31, wid = tid >> 5;
    unsigned v = ls;
    #pragma unroll
    for (int off = 1; off < 32; off <<= 1) {
        unsigned w2 = __shfl_down_sync(0xffffffffu, v, off);
        if (lane + off < 32) v += w2;
    }
    if (lane == 0) sh.warpTot[wid] = v;
    __syncthreads();
    if (tid < NWARP) {
        unsigned wv = sh.warpTot[tid];
        unsigned ws = wv;
        #pragma unroll
        for (int off = 1; off < NWARP; off <<= 1) {
            unsigned w2 = __shfl_down_sync(0xffffffffu, ws, off);
            if (tid + off < NWARP) ws += w2;
        }
        sh.warpSE[tid] = ws - wv;
    }
    __syncthreads();
    unsigned SE = sh.warpSE[wid] + (v - ls);
    if (basei < NB && SE < (unsigned)kRem && SE + ls >= (unsigned)kRem) {
        unsigned c = SE;
        #pragma unroll
        for (int j = CH - 1; j >= 0; j--) {
            unsigned hv = hist[basei + j];
            if (c + hv >= (unsigned)kRem) { sh.selBucket = basei + j; sh.selAbove = c; break; }
            c += hv;
        }
    }
    __syncthreads();
}

template<int F>
__device__ void run_scale(const float* __restrict__ pred,
                          const float* __restrict__ tb,
                          const int* __restrict__ tl,
                          float* __restrict__ out,
                          int b, int scale,
                          unsigned char* dyn, Sh& sh)
{
    constexpr int FSQ = F * F;
    constexpr int A = FSQ * 3;
    constexpr float STRIDE = 448.0f / (float)F;
    constexpr float INV = (float)F / 448.0f;   // exact (1/8, 1/16, 1/32)

    unsigned* s_iou = (unsigned*)(dyn + OFF_VAL);
    float* s_bce = (float*)(dyn + OFF_VAL);      // aliased: iou consumed -> bce stored
    unsigned* hist = (unsigned*)(dyn + OFF_HIST);

    const int tid = threadIdx.x;
    const int lane = tid & 31;

    if (tid < TGT) {
        const float* p = tb + (size_t)(b * TGT + tid) * 4;
        float x1 = p[0], y1 = p[1], x2 = p[2], y2 = p[3];
        sh.tb[tid][0] = x1; sh.tb[tid][1] = y1; sh.tb[tid][2] = x2; sh.tb[tid][3] = y2;
        sh.tarea[tid] = (x2 - x1) * (y2 - y1);
        sh.tlab[tid] = tl[b * TGT + tid];
        sh.best[tid] = 0ull;
        const float half3 = 1.5f * STRIDE;
        int c0 = max(0, (int)floorf((x1 - half3) * INV - 0.5f));
        int c1 = min(F - 1, (int)ceilf((x2 + half3) * INV - 0.5f));
        int r0 = max(0, (int)floorf((y1 - half3) * INV - 0.5f));
        int r1 = min(F - 1, (int)ceilf((y2 + half3) * INV - 0.5f));
        int w = c1 - c0 + 1, hh = r1 - r0 + 1;
        sh.rc0[tid] = c0; sh.rr0[tid] = r0;
        sh.rw[tid] = max(w, 1);
        sh.cum[tid] = (w > 0 && hh > 0) ? w * hh : 0;  // temp: size
    }
    for (int a = tid; a < A; a += BLOCK) s_iou[a] = 0u;
    for (int i = tid; i < 1024; i += BLOCK) hist[i] = 0;
    __syncthreads();
    if (tid == 0) {
        int s = 0;
        #pragma unroll
        for (int t = 0; t < TGT; t++) { int sz = sh.cum[t]; sh.cum[t] = s; s += sz; }
        sh.cum[TGT] = s;
    }
    __syncthreads();

    const float* predb = pred + (size_t)b * 24 * FSQ;

    // ---------- Phase 1: flattened (target,cell) scatter ----------
    {
        const int total = sh.cum[TGT];
        const int totalP = (total + BLOCK - 1) & ~(BLOCK - 1);
        int tcur = 0;
        for (int idx = tid; idx < totalP; idx += BLOCK) {
            bool valid = idx < total;
            int tt = -1;
            unsigned long long pk = 0ull;
            if (valid) {
                while (idx >= sh.cum[tcur + 1]) tcur++;
                tt = tcur;
                int local = idx - sh.cum[tt];
                int w = sh.rw[tt];
                int rr = local / w, cc = local - rr * w;
                int r = sh.rr0[tt] + rr, c = sh.rc0[tt] + cc;
                float cx = ((float)c + 0.5f) * STRIDE;
                float cy = ((float)r + 0.5f) * STRIDE;
                float tx1 = sh.tb[tt][0], ty1 = sh.tb[tt][1];
                float tx2 = sh.tb[tt][2], ty2 = sh.tb[tt][3];
                float ta = sh.tarea[tt];
                int abase = (r * F + c) * 3;
                #pragma unroll
                for (int ai = 0; ai < 3; ai++) {
                    float half = (1.0f + 0.25f * (float)ai) * STRIDE;
                    float lx = fmaxf(cx - half, tx1), ly = fmaxf(cy - half, ty1);
                    float rx = fminf(cx + half, tx2), ry = fminf(cy + half, ty2);
                    float iw = rx - lx, ih = ry - ly;
                    if (iw > 0.f && ih > 0.f) {
                        float I = iw * ih;
                        float areaA = (2.f * half) * (2.f * half);
                        float U = areaA + ta - I;
                        unsigned ib = __float_as_uint(I / (U + 1e-9f));
                        atomicMax(&s_iou[abase + ai], ib);
                        unsigned long long cand = ((unsigned long long)ib << 32) |
                            (unsigned long long)(0xffffffffu - (unsigned)(abase + ai));
                        if (cand > pk) pk = cand;
                    }
                }
            }
            #pragma unroll
            for (int off = 1; off < 32; off <<= 1) {
                unsigned long long opk = __shfl_up_sync(0xffffffffu, pk, off);
                int ot = __shfl_up_sync(0xffffffffu, tt, off);
                if (lane >= off && ot == tt && opk > pk) pk = opk;
            }
            unsigned mask = __match_any_sync(0xffffffffu, tt);
            int hi = 31 - __clz(mask);
            if (tt >= 0 && lane == hi && pk)
                atomicMax(&sh.best[tt], pk);
        }
    }
    __syncthreads();

    // ---------- Phase 2: forced-positive override marker (last target wins) ----------
    if (tid == 0) {
        #pragma unroll
        for (int t = 0; t < TGT; t++) {
            if (sh.best[t]) {
                unsigned a = 0xffffffffu - (unsigned)(sh.best[t] & 0xffffffffull);
                s_iou[a] = MARK + (unsigned)t;
            }
        }
    }
    __syncthreads();

    // ---------- Phase 3: BCE + fused level-0 hist + positive losses ----------
    float acc[5] = {0.f, 0.f, 0.f, 0.f, 0.f}; // posBce, ce, sl, cntPos, cntNeg
    constexpr int FSQP = ((FSQ + BLOCK - 1) / BLOCK) * BLOCK;
    for (int cell = tid; cell < FSQP; cell += BLOCK) {
        bool act = cell < FSQ;
        int row = 0, col = 0;
        float cx = 0.f, cy = 0.f;
        if (act) {
            row = cell / F; col = cell - row * F;
            cx = ((float)col + 0.5f) * STRIDE;
            cy = ((float)row + 0.5f) * STRIDE;
        }
        #pragma unroll
        for (int ai = 0; ai < 3; ai++) {
            int a = cell * 3 + ai;
            unsigned ib = 0; float x = 0.f;
            if (act) { ib = s_iou[a]; x = predb[(ai * 8 + 4) * FSQ + cell]; }
            bool forced = ib >= MARK;
            bool pos = forced || (act && ib >= 0x3F000000u);     // iou >= 0.5
            bool neg = act && !forced && ib < 0x3E99999Au;       // iou < 0.3
            float bce = fmaxf(x, 0.f) - (pos ? x : 0.f) + __logf(1.f + __expf(-fabsf(x)));
            if (act) s_bce[a] = neg ? -bce : bce;
            int bin = neg ? (int)(__float_as_uint(bce) >> 21) : -1;
            unsigned mask = __match_any_sync(0xffffffffu, bin);
            if (bin >= 0) {
                acc[4] += 1.f;
                if (lane == __ffs(mask) - 1) atomicAdd(&hist[bin], (unsigned)__popc(mask));
            }
            if (pos) {
                acc[3] += 1.f; acc[0] += bce;
                int t = 0;
                if (forced) t = (int)(ib - MARK);
                else {
                    #pragma unroll
                    for (int q = 0; q < TGT; q++) {
                        float half = (1.0f + 0.25f * (float)ai) * STRIDE;
                        float lx = fmaxf(cx - half, sh.tb[q][0]);
                        float ly = fmaxf(cy - half, sh.tb[q][1]);
                        float rx = fminf(cx + half, sh.tb[q][2]);
                        float ry = fminf(cy + half, sh.tb[q][3]);
                        float iw = rx - lx, ih = ry - ly;
                        if (iw > 0.f && ih > 0.f) {
                            float I = iw * ih;
                            float areaA = (2.f * half) * (2.f * half);
                            float U = areaA + sh.tarea[q] - I;
                            if (__float_as_uint(I / (U + 1e-9f)) == ib) { t = q; break; }
                        }
                    }
                }
                const float* pb = predb + cell;
                int cs = ai * 8;
                float c0v = pb[(cs + 5) * FSQ], c1v = pb[(cs + 6) * FSQ], c2v = pb[(cs + 7) * FSQ];
                float m = fmaxf(c0v, fmaxf(c1v, c2v));
                float lse = m + __logf(__expf(c0v - m) + __expf(c1v - m) + __expf(c2v - m));
                int tg = sh.tlab[t] - 1;
                float ct = (tg == 0) ? c0v : ((tg == 1) ? c1v : c2v);
                acc[1] += lse - ct;
                float half = (1.0f + 0.25f * (float)ai) * STRIDE;
                float aw = 2.f * half;
                float gx1 = sh.tb[t][0], gy1 = sh.tb[t][1];
                float gx2 = sh.tb[t][2], gy2 = sh.tb[t][3];
                float td[4] = { ((gx1 + gx2) * 0.5f - cx) / aw, ((gy1 + gy2) * 0.5f - cy) / aw,
                                __logf((gx2 - gx1) / aw), __logf((gy2 - gy1) / aw) };
                #pragma unroll
                for (int j = 0; j < 4; j++) {
                    float d = fabsf(pb[(cs + j) * FSQ] - td[j]);
                    acc[2] += (d < 1.f) ? 0.5f * d * d : d - 0.5f;
                }
            }
        }
    }
    redN<5>(acc, sh);
    float rPosBce = sh.out[0], rCe = sh.out[1], rSl = sh.out[2];
    int np = (int)sh.out[3], nn = (int)sh.out[4];
    int k = min(3 * np, nn);

    // ---------- Phase 4: hard-negative mining (R8-style full-A radix) ----------
    float negTop = 0.f;
    if (k > 0) {
        selectBucket<1024>(hist, k, sh);             // level 0: bits 30..21
        int Bq = sh.selBucket;
        int kRem = k - (int)sh.selAbove;

        for (int i = tid; i < 2048; i += BLOCK) hist[i] = 0;
        __syncthreads();
        for (int a = tid; a < A; a += BLOCK) {
            float v = s_bce[a];
            if (v < 0.f) {
                unsigned u = __float_as_uint(-v);
                if ((int)(u >> 21) == Bq) atomicAdd(&hist[(u >> 10) & 0x7ff], 1u);
            }
        }
        __syncthreads();
        selectBucket<2048>(hist, kRem, sh);          // level 1: bits 20..10
        int B2q = sh.selBucket;
        int kRem2 = kRem - (int)sh.selAbove;

        for (int i = tid; i < 1024; i += BLOCK) hist[i] = 0;
        __syncthreads();
        for (int a = tid; a < A; a += BLOCK) {
            float v = s_bce[a];
            if (v < 0.f) {
                unsigned u = __float_as_uint(-v);
                if ((int)(u >> 21) == Bq && (int)((u >> 10) & 0x7ff) == B2q)
                    atomicAdd(&hist[u & 0x3ff], 1u);
            }
        }
        __syncthreads();
        selectBucket<1024>(hist, kRem2, sh);         // level 2: bits 9..0
        unsigned thr_u = ((unsigned)Bq << 21) | ((unsigned)B2q << 10) | (unsigned)sh.selBucket;
        float thr = __uint_as_float(thr_u);

        float sc[2] = {0.f, 0.f};
        for (int a = tid; a < A; a += BLOCK) {
            float v = s_bce[a];
            if (v < 0.f) {
                unsigned u = __float_as_uint(-v);
                if (u > thr_u) { sc[0] += -v; sc[1] += 1.f; }
            }
        }
        redN<2>(sc, sh);
        negTop = sh.out[0] + (float)(k - (int)sh.out[1]) * thr;
    }

    // ---------- Phase 5: partials + fused last-block finalize ----------
    if (tid == 0) {
        float ol = (rPosBce + negTop) / (float)max(np + k, 1);
        float cl = rCe / (float)max(np, 1);
        float ll = rSl / (float)max(4 * np, 1);
        float* o = &g_partials[(scale * BATCH + b) * 3];
        o[0] = ol; o[1] = cl; o[2] = ll;
        __threadfence();
        unsigned r = atomicAdd(&g_done, 1);
        sh.isLast = (r == NBLK - 1) ? 1 : 0;
    }
    __syncthreads();
    if (sh.isLast) {
        float v[3] = {0.f, 0.f, 0.f};
        for (int i = tid; i < NBLK; i += BLOCK) {
            v[0] += g_partials[i * 3 + 0];
            v[1] += g_partials[i * 3 + 1];
            v[2] += g_partials[i * 3 + 2];
        }
        redN<3>(v, sh);
        if (tid == 0) {
            float obj = sh.out[0] / (float)BATCH;
            float cls = sh.out[1] / (float)BATCH;
            float loc = sh.out[2] / (float)BATCH;
            out[0] = obj; out[1] = cls; out[2] = loc;
            out[3] = obj + cls + 2.0f * loc;
            g_done = 0;  // reset for next graph replay
        }
    }
}

__global__ __launch_bounds__(BLOCK)
void loss_kernel(const float* __restrict__ pred1, const float* __restrict__ pred2,
                 const float* __restrict__ pred3,
                 const float* __restrict__ tb, const int* __restrict__ tl,
                 float* __restrict__ out)
{
    extern __shared__ unsigned char dyn[];
    __shared__ Sh sh;
    int b = blockIdx.x, scale = blockIdx.y;
    if (scale == 0)      run_scale<56>(pred1, tb, tl, out, b, 0, dyn, sh);
    else if (scale == 1) run_scale<28>(pred2, tb, tl, out, b, 1, dyn, sh);
    else                 run_scale<14>(pred3, tb, tl, out, b, 2, dyn, sh);
}

extern "C" void kernel_launch(void* const* d_in, const int* in_sizes, int n_in,
                              void* d_out, int out_size)
{
    const float* pred1 = (const float*)d_in[0];
    const float* pred2 = (const float*)d_in[1];
    const float* pred3 = (const float*)d_in[2];
    const float* tb    = (const float*)d_in[6];
    const int*   tl    = (const int*)d_in[7];

    cudaFuncSetAttribute(loss_kernel, cudaFuncAttributeMaxDynamicSharedMemorySize,
                         SMEM_BYTES);

    dim3 grid(BATCH, 3);
    loss_kernel<<<grid, BLOCK, SMEM_BYTES>>>(pred1, pred2, pred3, tb, tl, (float*)d_out);
}

// round 12
// speedup vs baseline: 3.0953x; 1.0455x over previous
#include <cuda_runtime.h>
#include <math.h>

#define TGT 20
#define BATCH 64
#define BLOCK 1024
#define NWARP (BLOCK / 32)
#define MAXA 9408
#define NBLK (3 * BATCH)
#define SEG 128                       // per-warp compaction segment (power of 2)

// dynamic smem layout (bytes)
#define OFF_VAL  0            // u32/f32[MAXA] 37632: iou bits -> bce (neg sign-enc)
#define OFF_HIST 37632        // u32[2048]  8192
#define OFF_LIST 45824        // f32[NWARP*SEG] 16384
#define SMEM_BYTES 62208

#define MARK 0x7F800001u      // forced-override marker base (NaN space)

struct Sh {
    float tb[TGT][4];
    float tarea[TGT];
    int   tlab[TGT];
    int   rc0[TGT], rr0[TGT], rw[TGT];
    int   cum[TGT + 1];
    unsigned long long best[TGT];
    float wred[NWARP][8];
    float out[8];
    unsigned warpTot[NWARP];
    unsigned warpSE[NWARP];
    unsigned wcnt[NWARP];
    int selBucket;
    unsigned selAbove;
    int overflow;
    int isLast;
};

__device__ float g_partials[NBLK * 3];
__device__ unsigned g_done = 0;

template<int N>
__device__ __forceinline__ void redN(float* v, Sh& sh) {
    int lane = threadIdx.x & 31, wid = threadIdx.x >> 5;
    #pragma unroll
    for (int i = 0; i < N; i++) {
        float x = v[i];
        #pragma unroll
        for (int off = 16; off; off >>= 1) x += __shfl_xor_sync(0xffffffffu, x, off);
        if (lane == 0) sh.wred[wid][i] = x;
    }
    __syncthreads();
    if (threadIdx.x < N) {
        float s = 0.f;
        #pragma unroll
        for (int w = 0; w < NWARP; w++) s += sh.wred[w][threadIdx.x];
        sh.out[threadIdx.x] = s;
    }
    __syncthreads();
}

template<int NB>
__device__ void selectBucket(unsigned* hist, int kRem, Sh& sh) {
    const int tid = threadIdx.x;
    constexpr int CH = (NB >= BLOCK) ? NB / BLOCK : 1;
    int basei = tid * CH;
    unsigned ls = 0;
    if (basei < NB)
        #pragma unroll
        for (int j = 0; j < CH; j++) ls += hist[basei + j];
    int lane = tid & 31, wid = tid >> 5;
    unsigned v = ls;
    #pragma unroll
    for (int off = 1; off < 32; off <<= 1) {
        unsigned w2 = __shfl_down_sync(0xffffffffu, v, off);
        if (lane + off < 32) v += w2;
    }
    if (lane == 0) sh.warpTot[wid] = v;
    __syncthreads();
    if (tid < NWARP) {
        unsigned wv = sh.warpTot[tid];
        unsigned ws = wv;
        #pragma unroll
        for (int off = 1; off < NWARP; off <<= 1) {
            unsigned w2 = __shfl_down_sync(0xffffffffu, ws, off);
            if (tid + off < NWARP) ws += w2;
        }
        sh.warpSE[tid] = ws - wv;
    }
    __syncthreads();
    unsigned SE = sh.warpSE[wid] + (v - ls);
    if (basei < NB && SE < (unsigned)kRem && SE + ls >= (unsigned)kRem) {
        unsigned c = SE;
        #pragma unroll
        for (int j = CH - 1; j >= 0; j--) {
            unsigned hv = hist[basei + j];
            if (c + hv >= (unsigned)kRem) { sh.selBucket = basei + j; sh.selAbove = c; break; }
            c += hv;
        }
    }
    __syncthreads();
}

template<int F>
__device__ void run_scale(const float* __restrict__ pred,
                          const float* __restrict__ tb,
                          const int* __restrict__ tl,
                          float* __restrict__ out,
                          int b, int scale,
                          unsigned char* dyn, Sh& sh)
{
    constexpr int FSQ = F * F;
    constexpr int A = FSQ * 3;
    constexpr float STRIDE = 448.0f / (float)F;
    constexpr float INV = (float)F / 448.0f;   // exact (1/8, 1/16, 1/32)

    unsigned* s_iou = (unsigned*)(dyn + OFF_VAL);
    float* s_bce = (float*)(dyn + OFF_VAL);      // aliased: iou consumed -> bce stored
    unsigned* hist = (unsigned*)(dyn + OFF_HIST);
    float* list = (float*)(dyn + OFF_LIST);

    const int tid = threadIdx.x;
    const int lane = tid & 31;
    const int wid = tid >> 5;

    if (tid < TGT) {
        const float* p = tb + (size_t)(b * TGT + tid) * 4;
        float x1 = p[0], y1 = p[1], x2 = p[2], y2 = p[3];
        sh.tb[tid][0] = x1; sh.tb[tid][1] = y1; sh.tb[tid][2] = x2; sh.tb[tid][3] = y2;
        sh.tarea[tid] = (x2 - x1) * (y2 - y1);
        sh.tlab[tid] = tl[b * TGT + tid];
        sh.best[tid] = 0ull;
        const float half3 = 1.5f * STRIDE;
        int c0 = max(0, (int)floorf((x1 - half3) * INV - 0.5f));
        int c1 = min(F - 1, (int)ceilf((x2 + half3) * INV - 0.5f));
        int r0 = max(0, (int)floorf((y1 - half3) * INV - 0.5f));
        int r1 = min(F - 1, (int)ceilf((y2 + half3) * INV - 0.5f));
        int w = c1 - c0 + 1, hh = r1 - r0 + 1;
        sh.rc0[tid] = c0; sh.rr0[tid] = r0;
        sh.rw[tid] = max(w, 1);
        sh.cum[tid] = (w > 0 && hh > 0) ? w * hh : 0;  // temp: size
    }
    {
        uint4 z4 = make_uint4(0u, 0u, 0u, 0u);
        uint4* p4 = (uint4*)s_iou;
        for (int i = tid; i < A / 4; i += BLOCK) p4[i] = z4;
    }
    for (int i = tid; i < 1024; i += BLOCK) hist[i] = 0;
    __syncthreads();
    if (tid == 0) {
        int s = 0;
        #pragma unroll
        for (int t = 0; t < TGT; t++) { int sz = sh.cum[t]; sh.cum[t] = s; s += sz; }
        sh.cum[TGT] = s;
    }
    __syncthreads();

    const float* predb = pred + (size_t)b * 24 * FSQ;

    // ---------- Phase 1: flattened (target,cell) scatter ----------
    {
        const int total = sh.cum[TGT];
        const int totalP = (total + BLOCK - 1) & ~(BLOCK - 1);
        int tcur = 0;
        for (int idx = tid; idx < totalP; idx += BLOCK) {
            bool valid = idx < total;
            int tt = -1;
            unsigned long long pk = 0ull;
            if (valid) {
                while (idx >= sh.cum[tcur + 1]) tcur++;
                tt = tcur;
                int local = idx - sh.cum[tt];
                int w = sh.rw[tt];
                int rr = local / w, cc = local - rr * w;
                int r = sh.rr0[tt] + rr, c = sh.rc0[tt] + cc;
                float cx = ((float)c + 0.5f) * STRIDE;
                float cy = ((float)r + 0.5f) * STRIDE;
                float tx1 = sh.tb[tt][0], ty1 = sh.tb[tt][1];
                float tx2 = sh.tb[tt][2], ty2 = sh.tb[tt][3];
                float ta = sh.tarea[tt];
                int abase = (r * F + c) * 3;
                #pragma unroll
                for (int ai = 0; ai < 3; ai++) {
                    float half = (1.0f + 0.25f * (float)ai) * STRIDE;
                    float lx = fmaxf(cx - half, tx1), ly = fmaxf(cy - half, ty1);
                    float rx = fminf(cx + half, tx2), ry = fminf(cy + half, ty2);
                    float iw = rx - lx, ih = ry - ly;
                    if (iw > 0.f && ih > 0.f) {
                        float I = iw * ih;
                        float areaA = (2.f * half) * (2.f * half);
                        float U = areaA + ta - I;
                        unsigned ib = __float_as_uint(__fdividef(I, U + 1e-9f));
                        atomicMax(&s_iou[abase + ai], ib);
                        unsigned long long cand = ((unsigned long long)ib << 32) |
                            (unsigned long long)(0xffffffffu - (unsigned)(abase + ai));
                        if (cand > pk) pk = cand;
                    }
                }
            }
            #pragma unroll
            for (int off = 1; off < 32; off <<= 1) {
                unsigned long long opk = __shfl_up_sync(0xffffffffu, pk, off);
                int ot = __shfl_up_sync(0xffffffffu, tt, off);
                if (lane >= off && ot == tt && opk > pk) pk = opk;
            }
            unsigned mask = __match_any_sync(0xffffffffu, tt);
            int hi = 31 - __clz(mask);
            if (tt >= 0 && lane == hi && pk)
                atomicMax(&sh.best[tt], pk);
        }
    }
    __syncthreads();

    // ---------- Phase 2: forced-positive override marker (last target wins) ----------
    if (tid == 0) {
        #pragma unroll
        for (int t = 0; t < TGT; t++) {
            if (sh.best[t]) {
                unsigned a = 0xffffffffu - (unsigned)(sh.best[t] & 0xffffffffull);
                s_iou[a] = MARK + (unsigned)t;
            }
        }
    }
    __syncthreads();

    // ---------- Phase 3: BCE + fused level-0 hist + positive losses ----------
    float acc[5] = {0.f, 0.f, 0.f, 0.f, 0.f}; // posBce, ce, sl, cntPos, cntNeg
    constexpr int FSQP = ((FSQ + BLOCK - 1) / BLOCK) * BLOCK;
    for (int cell = tid; cell < FSQP; cell += BLOCK) {
        bool act = cell < FSQ;
        int row = 0, col = 0;
        float cx = 0.f, cy = 0.f;
        if (act) {
            row = cell / F; col = cell - row * F;
            cx = ((float)col + 0.5f) * STRIDE;
            cy = ((float)row + 0.5f) * STRIDE;
        }
        #pragma unroll
        for (int ai = 0; ai < 3; ai++) {
            int a = cell * 3 + ai;
            unsigned ib = 0; float x = 0.f;
            if (act) { ib = s_iou[a]; x = predb[(ai * 8 + 4) * FSQ + cell]; }
            bool forced = ib >= MARK;
            bool pos = forced || (act && ib >= 0x3F000000u);     // iou >= 0.5
            bool neg = act && !forced && ib < 0x3E99999Au;       // iou < 0.3
            float bce = fmaxf(x, 0.f) - (pos ? x : 0.f) + __logf(1.f + __expf(-fabsf(x)));
            if (act) s_bce[a] = neg ? -bce : bce;
            int bin = neg ? (int)(__float_as_uint(bce) >> 21) : -1;
            unsigned mask = __match_any_sync(0xffffffffu, bin);
            if (bin >= 0) {
                acc[4] += 1.f;
                if (lane == __ffs(mask) - 1) atomicAdd(&hist[bin], (unsigned)__popc(mask));
            }
            if (pos) {
                acc[3] += 1.f; acc[0] += bce;
                int t = 0;
                if (forced) t = (int)(ib - MARK);
                else {
                    #pragma unroll
                    for (int q = 0; q < TGT; q++) {
                        float half = (1.0f + 0.25f * (float)ai) * STRIDE;
                        float lx = fmaxf(cx - half, sh.tb[q][0]);
                        float ly = fmaxf(cy - half, sh.tb[q][1]);
                        float rx = fminf(cx + half, sh.tb[q][2]);
                        float ry = fminf(cy + half, sh.tb[q][3]);
                        float iw = rx - lx, ih = ry - ly;
                        if (iw > 0.f && ih > 0.f) {
                            float I = iw * ih;
                            float areaA = (2.f * half) * (2.f * half);
                            float U = areaA + sh.tarea[q] - I;
                            if (__float_as_uint(__fdividef(I, U + 1e-9f)) == ib) { t = q; break; }
                        }
                    }
                }
                const float* pb = predb + cell;
                int cs = ai * 8;
                float c0v = pb[(cs + 5) * FSQ], c1v = pb[(cs + 6) * FSQ], c2v = pb[(cs + 7) * FSQ];
                float m = fmaxf(c0v, fmaxf(c1v, c2v));
                float lse = m + __logf(__expf(c0v - m) + __expf(c1v - m) + __expf(c2v - m));
                int tg = sh.tlab[t] - 1;
                float ct = (tg == 0) ? c0v : ((tg == 1) ? c1v : c2v);
                acc[1] += lse - ct;
                float half = (1.0f + 0.25f * (float)ai) * STRIDE;
                float aw = 2.f * half;
                float gx1 = sh.tb[t][0], gy1 = sh.tb[t][1];
                float gx2 = sh.tb[t][2], gy2 = sh.tb[t][3];
                float td[4] = { __fdividef((gx1 + gx2) * 0.5f - cx, aw),
                                __fdividef((gy1 + gy2) * 0.5f - cy, aw),
                                __logf(__fdividef(gx2 - gx1, aw)),
                                __logf(__fdividef(gy2 - gy1, aw)) };
                #pragma unroll
                for (int j = 0; j < 4; j++) {
                    float d = fabsf(pb[(cs + j) * FSQ] - td[j]);
                    acc[2] += (d < 1.f) ? 0.5f * d * d : d - 0.5f;
                }
            }
        }
    }
    redN<5>(acc, sh);
    float rPosBce = sh.out[0], rCe = sh.out[1], rSl = sh.out[2];
    int np = (int)sh.out[3], nn = (int)sh.out[4];
    int k = min(3 * np, nn);

    // ---------- Phase 4: hard-negative mining ----------
    float negTop = 0.f;
    if (k > 0) {
        selectBucket<1024>(hist, k, sh);             // level 0: bits 30..21
        int Bq = sh.selBucket;
        int kAbove0 = (int)sh.selAbove;
        int kRem = k - kAbove0;

        if (tid == 0) sh.overflow = 0;
        for (int i = tid; i < 2048; i += BLOCK) hist[i] = 0;
        __syncthreads();

        // single PADDED full-A pass: sumAbove + per-warp segment compaction
        // + level-1 hist. Loop padded to BLOCK multiple: warp collectives
        // below require all lanes present (A=2352/588 are NOT warp multiples).
        constexpr int APAD = ((A + BLOCK - 1) / BLOCK) * BLOCK;
        float sa[1] = {0.f};
        unsigned cnt = 0;
        float* seg = list + wid * SEG;
        for (int a = tid; a < APAD; a += BLOCK) {
            bool act = a < A;
            float v = act ? s_bce[a] : 1.0f;         // positive -> not neg
            bool isneg = v < 0.f;
            float bce = -v;
            unsigned u = __float_as_uint(bce);
            int bk = isneg ? (int)(u >> 21) : -1;
            if (bk > Bq) sa[0] += bce;
            bool inB = (bk == Bq);
            unsigned bal = __ballot_sync(0xffffffffu, inB);
            if (inB) {
                unsigned pos = cnt + (unsigned)__popc(bal & ((1u << lane) - 1u));
                if (pos < SEG) seg[pos] = bce;
            }
            cnt += (unsigned)__popc(bal);
            int b1 = inB ? (int)((u >> 10) & 0x7ff) : -1;
            unsigned mm = __match_any_sync(0xffffffffu, b1);
            if (b1 >= 0 && lane == __ffs(mm) - 1)
                atomicAdd(&hist[b1], (unsigned)__popc(mm));
        }
        if (lane == 0) {
            sh.wcnt[wid] = cnt;
            if (cnt > SEG) sh.overflow = 1;
        }
        redN<1>(sa, sh);                             // syncs; publishes wcnt/overflow
        float sumAbove = sh.out[0];
        int ovf = sh.overflow;                       // block-uniform after sync

        selectBucket<2048>(hist, kRem, sh);          // level 1: bits 20..10
        int B2q = sh.selBucket;
        int kRem2 = kRem - (int)sh.selAbove;

        for (int i = tid; i < 1024; i += BLOCK) hist[i] = 0;
        __syncthreads();

        if (!ovf) {
            // level-2 hist + threshold passes over flat segment list
            for (int s = tid; s < NWARP * SEG; s += BLOCK) {
                if ((unsigned)(s & (SEG - 1)) < sh.wcnt[s / SEG]) {
                    unsigned u = __float_as_uint(list[s]);
                    if (((u >> 10) & 0x7ff) == (unsigned)B2q) atomicAdd(&hist[u & 0x3ff], 1u);
                }
            }
            __syncthreads();
            selectBucket<1024>(hist, kRem2, sh);     // level 2: bits 9..0
            unsigned thr_u = ((unsigned)Bq << 21) | ((unsigned)B2q << 10) | (unsigned)sh.selBucket;
            float thr = __uint_as_float(thr_u);
            float sc[2] = {0.f, 0.f};
            for (int s = tid; s < NWARP * SEG; s += BLOCK) {
                if ((unsigned)(s & (SEG - 1)) < sh.wcnt[s / SEG]) {
                    float v = list[s];
                    if (__float_as_uint(v) > thr_u) { sc[0] += v; sc[1] += 1.f; }
                }
            }
            redN<2>(sc, sh);
            negTop = sumAbove + sh.out[0] + (float)(k - kAbove0 - (int)sh.out[1]) * thr;
        } else {
            // fallback: full-A level-2 + threshold passes (exact, R10 path)
            for (int a = tid; a < A; a += BLOCK) {
                float v = s_bce[a];
                if (v < 0.f) {
                    unsigned u = __float_as_uint(-v);
                    if ((int)(u >> 21) == Bq && (int)((u >> 10) & 0x7ff) == B2q)
                        atomicAdd(&hist[u & 0x3ff], 1u);
                }
            }
            __syncthreads();
            selectBucket<1024>(hist, kRem2, sh);
            unsigned thr_u = ((unsigned)Bq << 21) | ((unsigned)B2q << 10) | (unsigned)sh.selBucket;
            float thr = __uint_as_float(thr_u);
            float sc[2] = {0.f, 0.f};
            for (int a = tid; a < A; a += BLOCK) {
                float v = s_bce[a];
                if (v < 0.f) {
                    unsigned u = __float_as_uint(-v);
                    if (u > thr_u) { sc[0] += -v; sc[1] += 1.f; }
                }
            }
            redN<2>(sc, sh);
            negTop = sh.out[0] + (float)(k - (int)sh.out[1]) * thr;
        }
    }

    // ---------- Phase 5: partials + fused last-block finalize ----------
    if (tid == 0) {
        float ol = (rPosBce + negTop) / (float)max(np + k, 1);
        float cl = rCe / (float)max(np, 1);
        float ll = rSl / (float)max(4 * np, 1);
        float* o = &g_partials[(scale * BATCH + b) * 3];
        o[0] = ol; o[1] = cl; o[2] = ll;
        __threadfence();
        unsigned r = atomicAdd(&g_done, 1);
        sh.isLast = (r == NBLK - 1) ? 1 : 0;
    }
    __syncthreads();
    if (sh.isLast) {
        float v[3] = {0.f, 0.f, 0.f};
        for (int i = tid; i < NBLK; i += BLOCK) {
            v[0] += g_partials[i * 3 + 0];
            v[1] += g_partials[i * 3 + 1];
            v[2] += g_partials[i * 3 + 2];
        }
        redN<3>(v, sh);
        if (tid == 0) {
            float obj = sh.out[0] / (float)BATCH;
            float cls = sh.out[1] / (float)BATCH;
            float loc = sh.out[2] / (float)BATCH;
            out[0] = obj; out[1] = cls; out[2] = loc;
            out[3] = obj + cls + 2.0f * loc;
            g_done = 0;  // reset for next graph replay
        }
    }
}

__global__ __launch_bounds__(BLOCK)
void loss_kernel(const float* __restrict__ pred1, const float* __restrict__ pred2,
                 const float* __restrict__ pred3,
                 const float* __restrict__ tb, const int* __restrict__ tl,
                 float* __restrict__ out)
{
    extern __shared__ unsigned char dyn[];
    __shared__ Sh sh;
    int b = blockIdx.x, scale = blockIdx.y;
    if (scale == 0)      run_scale<56>(pred1, tb, tl, out, b, 0, dyn, sh);
    else if (scale == 1) run_scale<28>(pred2, tb, tl, out, b, 1, dyn, sh);
    else                 run_scale<14>(pred3, tb, tl, out, b, 2, dyn, sh);
}

extern "C" void kernel_launch(void* const* d_in, const int* in_sizes, int n_in,
                              void* d_out, int out_size)
{
    const float* pred1 = (const float*)d_in[0];
    const float* pred2 = (const float*)d_in[1];
    const float* pred3 = (const float*)d_in[2];
    const float* tb    = (const float*)d_in[6];
    const int*   tl    = (const int*)d_in[7];

    cudaFuncSetAttribute(loss_kernel, cudaFuncAttributeMaxDynamicSharedMemorySize,
                         SMEM_BYTES);

    dim3 grid(BATCH, 3);
    loss_kernel<<<grid, BLOCK, SMEM_BYTES>>>(pred1, pred2, pred3, tb, tl, (float*)d_out);
}